// round 1
// baseline (speedup 1.0000x reference)
#include <cuda_runtime.h>
#include <cuda_bf16.h>
#include <math.h>

// Problem constants
#define BS    2048
#define LTOK  49
#define DMODEL 512
#define NHEAD 16
#define HDIM  32
#define NMASK 64
#define MROWS (BS * LTOK)          // 100352
#define N_QKV (3 * DMODEL)         // 1536

// Scratch (device globals: allocation-free per harness rules)
__device__ float g_qkv[(size_t)MROWS * N_QKV];   // [100352, 1536]
__device__ float g_ctx[(size_t)MROWS * DMODEL];  // [100352, 512]

// ---------------------------------------------------------------------------
// SGEMM: C[M,N] = A[M,K] @ B[K,N] + bias[N]
// BM=BN=128, BK=8, 256 threads, 8x8 per thread, float4 global loads.
// Assumes M%128==0, N%128==0, K%8==0 (true for all calls here).
// ---------------------------------------------------------------------------
#define BM 128
#define BN 128
#define BKK 8
#define TM 8
#define TN 8

__global__ __launch_bounds__(256) void sgemm_bias(
    const float* __restrict__ A, const float* __restrict__ B,
    const float* __restrict__ bias, float* __restrict__ C,
    int M, int N, int K)
{
    __shared__ float As[BKK][BM];
    __shared__ float Bs[BKK][BN];

    const int tid = threadIdx.x;
    const int bm = blockIdx.y * BM;
    const int bn = blockIdx.x * BN;

    // Global-load mapping
    const int a_row = tid >> 1;          // 0..127
    const int a_col = (tid & 1) << 2;    // 0 or 4
    const int b_row = tid >> 5;          // 0..7
    const int b_col = (tid & 31) << 2;   // 0..124 step 4

    // Compute mapping
    const int tx = (tid & 15) * TN;      // col offset in tile
    const int ty = (tid >> 4) * TM;      // row offset in tile

    float acc[TM][TN];
    #pragma unroll
    for (int i = 0; i < TM; i++)
        #pragma unroll
        for (int j = 0; j < TN; j++) acc[i][j] = 0.0f;

    for (int k0 = 0; k0 < K; k0 += BKK) {
        float4 av = *(const float4*)(A + (size_t)(bm + a_row) * K + k0 + a_col);
        As[a_col + 0][a_row] = av.x;
        As[a_col + 1][a_row] = av.y;
        As[a_col + 2][a_row] = av.z;
        As[a_col + 3][a_row] = av.w;
        float4 bv = *(const float4*)(B + (size_t)(k0 + b_row) * N + bn + b_col);
        *(float4*)&Bs[b_row][b_col] = bv;
        __syncthreads();

        #pragma unroll
        for (int kk = 0; kk < BKK; kk++) {
            float ra[TM], rb[TN];
            #pragma unroll
            for (int i = 0; i < TM; i++) ra[i] = As[kk][ty + i];
            #pragma unroll
            for (int j = 0; j < TN; j++) rb[j] = Bs[kk][tx + j];
            #pragma unroll
            for (int i = 0; i < TM; i++)
                #pragma unroll
                for (int j = 0; j < TN; j++)
                    acc[i][j] = fmaf(ra[i], rb[j], acc[i][j]);
        }
        __syncthreads();
    }

    // Epilogue: add bias, store float4
    float bvals[TN];
    #pragma unroll
    for (int j = 0; j < TN; j++) bvals[j] = bias[bn + tx + j];

    #pragma unroll
    for (int i = 0; i < TM; i++) {
        size_t row = (size_t)(bm + ty + i);
        float4 o0, o1;
        o0.x = acc[i][0] + bvals[0]; o0.y = acc[i][1] + bvals[1];
        o0.z = acc[i][2] + bvals[2]; o0.w = acc[i][3] + bvals[3];
        o1.x = acc[i][4] + bvals[4]; o1.y = acc[i][5] + bvals[5];
        o1.z = acc[i][6] + bvals[6]; o1.w = acc[i][7] + bvals[7];
        *(float4*)(C + row * N + bn + tx + 0) = o0;
        *(float4*)(C + row * N + bn + tx + 4) = o1;
    }
}

// ---------------------------------------------------------------------------
// Attention: one block per (window b, head h). 256 threads.
//   q,k,v: [49,32] tiles gathered from g_qkv.
//   S = qk^T/sqrt(32) + bias_table[rel_index][h] + mask[(b*16+h)%64]
//   P = softmax(S, rows); ctx = P @ v, stored [bs, L, D] layout.
// ---------------------------------------------------------------------------
__global__ __launch_bounds__(256) void attn_kernel(
    const float* __restrict__ bias_table,
    const int*   __restrict__ rel_index,
    const float* __restrict__ mask)
{
    __shared__ float qs[LTOK * 32];
    __shared__ float ks[LTOK * 33];   // padded: kills 32-stride bank conflicts
    __shared__ float vs[LTOK * 32];
    __shared__ float sc[LTOK * LTOK];

    const int bh = blockIdx.x;
    const int b = bh >> 4;
    const int h = bh & 15;
    const int w = bh & (NMASK - 1);   // (b*16+h) % 64 — faithful to jnp.tile
    const int tid = threadIdx.x;
    const float scale = 0.17677669529663687f; // 1/sqrt(32)

    // Load q (pre-scaled), k, v
    for (int t = tid; t < LTOK * 32; t += 256) {
        int l = t >> 5, c = t & 31;
        size_t base = ((size_t)(b * LTOK + l)) * N_QKV + h * HDIM + c;
        qs[l * 32 + c] = g_qkv[base] * scale;
        ks[l * 33 + c] = g_qkv[base + DMODEL];
        vs[l * 32 + c] = g_qkv[base + 2 * DMODEL];
    }
    __syncthreads();

    // Scores
    const float* mrow = mask + (size_t)w * LTOK * LTOK;
    for (int idx = tid; idx < LTOK * LTOK; idx += 256) {
        int i = idx / LTOK, j = idx - i * LTOK;
        float s = 0.0f;
        #pragma unroll
        for (int kk = 0; kk < 32; kk++)
            s = fmaf(qs[i * 32 + kk], ks[j * 33 + kk], s);
        int ri = __ldg(&rel_index[idx]);
        s += __ldg(&bias_table[ri * NHEAD + h]);
        s += __ldg(&mrow[idx]);
        sc[idx] = s;
    }
    __syncthreads();

    // Softmax: warp per row (8 warps, rows i = warp, warp+8, ...)
    const int warp = tid >> 5, lane = tid & 31;
    for (int i = warp; i < LTOK; i += 8) {
        float m = -1e30f;
        for (int j = lane; j < LTOK; j += 32) m = fmaxf(m, sc[i * LTOK + j]);
        #pragma unroll
        for (int o = 16; o; o >>= 1) m = fmaxf(m, __shfl_xor_sync(0xffffffffu, m, o));
        float sum = 0.0f;
        for (int j = lane; j < LTOK; j += 32) {
            float e = expf(sc[i * LTOK + j] - m);
            sc[i * LTOK + j] = e;
            sum += e;
        }
        #pragma unroll
        for (int o = 16; o; o >>= 1) sum += __shfl_xor_sync(0xffffffffu, sum, o);
        float inv = 1.0f / sum;
        for (int j = lane; j < LTOK; j += 32) sc[i * LTOK + j] *= inv;
    }
    __syncthreads();

    // ctx = P @ v  -> g_ctx[(b*49+i)*512 + h*32 + c]
    for (int idx = tid; idx < LTOK * 32; idx += 256) {
        int i = idx >> 5, c = idx & 31;
        float acc = 0.0f;
        #pragma unroll 7
        for (int j = 0; j < LTOK; j++)
            acc = fmaf(sc[i * LTOK + j], vs[j * 32 + c], acc);
        g_ctx[((size_t)(b * LTOK + i)) * DMODEL + h * HDIM + c] = acc;
    }
}

// ---------------------------------------------------------------------------
// Launch
// ---------------------------------------------------------------------------
extern "C" void kernel_launch(void* const* d_in, const int* in_sizes, int n_in,
                              void* d_out, int out_size)
{
    const float* x          = (const float*)d_in[0];
    const float* w_qkv      = (const float*)d_in[1];
    const float* b_qkv      = (const float*)d_in[2];
    const float* w_out      = (const float*)d_in[3];
    const float* b_out      = (const float*)d_in[4];
    const float* bias_table = (const float*)d_in[5];
    const float* mask       = (const float*)d_in[6];
    const int*   rel_index  = (const int*)d_in[7];
    float*       out        = (float*)d_out;

    float* qkv_ptr = nullptr;
    float* ctx_ptr = nullptr;
    cudaGetSymbolAddress((void**)&qkv_ptr, g_qkv);
    cudaGetSymbolAddress((void**)&ctx_ptr, g_ctx);

    // QKV projection: [100352,512] @ [512,1536] + b_qkv
    dim3 g1(N_QKV / BN, MROWS / BM);
    sgemm_bias<<<g1, 256>>>(x, w_qkv, b_qkv, qkv_ptr, MROWS, N_QKV, DMODEL);

    // Attention per (window, head)
    attn_kernel<<<BS * NHEAD, 256>>>(bias_table, rel_index, mask);

    // Output projection: [100352,512] @ [512,512] + b_out
    dim3 g2(DMODEL / BN, MROWS / BM);
    sgemm_bias<<<g2, 256>>>(ctx_ptr, w_out, b_out, out, MROWS, DMODEL, DMODEL);
}

// round 3
// speedup vs baseline: 1.9138x; 1.9138x over previous
#include <cuda_runtime.h>
#include <cuda_bf16.h>
#include <math.h>
#include <stdint.h>

// Problem constants
#define BS     2048
#define LTOK   49
#define DMODEL 512
#define NHEAD  16
#define HDIM   32
#define NMASK  64
#define MROWS  (BS * LTOK)          // 100352
#define N_QKV  (3 * DMODEL)         // 1536

// Scratch (device globals: allocation-free per harness rules)
__device__ float g_qkv[(size_t)MROWS * N_QKV];            // [100352, 1536] f32
__device__ __nv_bfloat16 g_x_hi[(size_t)MROWS * DMODEL];
__device__ __nv_bfloat16 g_x_lo[(size_t)MROWS * DMODEL];
__device__ __nv_bfloat16 g_ctx_hi[(size_t)MROWS * DMODEL];
__device__ __nv_bfloat16 g_ctx_lo[(size_t)MROWS * DMODEL];
// Transposed + hi/lo-split weights: [N, K] bf16, K-major
__device__ __nv_bfloat16 g_wqkvT_hi[(size_t)N_QKV * DMODEL];
__device__ __nv_bfloat16 g_wqkvT_lo[(size_t)N_QKV * DMODEL];
__device__ __nv_bfloat16 g_woutT_hi[(size_t)DMODEL * DMODEL];
__device__ __nv_bfloat16 g_woutT_lo[(size_t)DMODEL * DMODEL];

// ---------------------------------------------------------------------------
// PTX helpers (sm_80-compatible: cp.async + ldmatrix + mma.sync only)
// ---------------------------------------------------------------------------
__device__ __forceinline__ uint32_t smem_u32(const void* p) {
    uint32_t a;
    asm("{ .reg .u64 t; cvta.to.shared.u64 t, %1; cvt.u32.u64 %0, t; }" : "=r"(a) : "l"(p));
    return a;
}
#define CP_ASYNC16(dst, src) \
    asm volatile("cp.async.cg.shared.global [%0], [%1], 16;" :: "r"(dst), "l"(src))
#define CP_COMMIT() asm volatile("cp.async.commit_group;" ::: "memory")
#define CP_WAIT(n)  asm volatile("cp.async.wait_group %0;" :: "n"(n) : "memory")

__device__ __forceinline__ void ldmx4(uint32_t* r, uint32_t addr) {
    asm volatile("ldmatrix.sync.aligned.m8n8.x4.shared.b16 {%0,%1,%2,%3}, [%4];"
                 : "=r"(r[0]), "=r"(r[1]), "=r"(r[2]), "=r"(r[3]) : "r"(addr));
}
__device__ __forceinline__ void mma16816(float* d, const uint32_t* a, const uint32_t* b) {
    asm volatile(
        "mma.sync.aligned.m16n8k16.row.col.f32.bf16.bf16.f32 "
        "{%0,%1,%2,%3}, {%4,%5,%6,%7}, {%8,%9}, {%0,%1,%2,%3};"
        : "+f"(d[0]), "+f"(d[1]), "+f"(d[2]), "+f"(d[3])
        : "r"(a[0]), "r"(a[1]), "r"(a[2]), "r"(a[3]), "r"(b[0]), "r"(b[1]));
}

// ---------------------------------------------------------------------------
// Prep kernels: f32 -> bf16 hi/lo split (x elementwise; weights transposed)
// ---------------------------------------------------------------------------
__global__ void prep_split_x(const float* __restrict__ x,
                             __nv_bfloat16* __restrict__ hi,
                             __nv_bfloat16* __restrict__ lo, int n4)
{
    int i = blockIdx.x * blockDim.x + threadIdx.x;
    if (i >= n4) return;
    float4 v = ((const float4*)x)[i];
    __nv_bfloat162 h01 = __floats2bfloat162_rn(v.x, v.y);
    __nv_bfloat162 h23 = __floats2bfloat162_rn(v.z, v.w);
    __nv_bfloat162 l01 = __floats2bfloat162_rn(v.x - __bfloat162float(h01.x),
                                               v.y - __bfloat162float(h01.y));
    __nv_bfloat162 l23 = __floats2bfloat162_rn(v.z - __bfloat162float(h23.x),
                                               v.w - __bfloat162float(h23.y));
    ((__nv_bfloat162*)hi)[i * 2 + 0] = h01;
    ((__nv_bfloat162*)hi)[i * 2 + 1] = h23;
    ((__nv_bfloat162*)lo)[i * 2 + 0] = l01;
    ((__nv_bfloat162*)lo)[i * 2 + 1] = l23;
}

__global__ void prep_split_w(const float* __restrict__ W,
                             __nv_bfloat16* __restrict__ Wt_hi,
                             __nv_bfloat16* __restrict__ Wt_lo,
                             int K, int N)
{
    int idx = blockIdx.x * blockDim.x + threadIdx.x;   // n*K + k
    if (idx >= K * N) return;
    int n = idx / K, k = idx - n * K;
    float w = W[(size_t)k * N + n];
    __nv_bfloat16 hi = __float2bfloat16(w);
    Wt_hi[idx] = hi;
    Wt_lo[idx] = __float2bfloat16(w - __bfloat162float(hi));
}

// ---------------------------------------------------------------------------
// mma.sync GEMM: C[M,N] = (Ah+Al)[M,K] @ (Bh+Bl)[N,K]^T + bias (fp32 acc)
// 3-term split: Ah*Bh + Ah*Bl + Al*Bh.
// 128x128 tile, BK=32, 256 threads (8 warps, warp tile 64x32),
// 2-stage cp.async double buffer, padded smem rows (40 bf16 = 80B).
// ---------------------------------------------------------------------------
#define GBM 128
#define GBN 128
#define GBK 32
#define ROWB 80                         // bytes per smem row (32 + 8 pad bf16)
#define TILEB (128 * ROWB)              // 10240
#define STAGEB (4 * TILEB)              // 40960
#define SM_AH 0
#define SM_AL TILEB
#define SM_BH (2 * TILEB)
#define SM_BL (3 * TILEB)
#define SM_TOTAL (2 * STAGEB)           // 81920

__global__ __launch_bounds__(256) void gemm_mma(
    const __nv_bfloat16* __restrict__ Ah, const __nv_bfloat16* __restrict__ Al,
    const __nv_bfloat16* __restrict__ Bh, const __nv_bfloat16* __restrict__ Bl,
    const float* __restrict__ bias, float* __restrict__ C,
    int M, int N, int K)
{
    extern __shared__ char smem[];
    const uint32_t sbase = smem_u32(smem);
    const int tid = threadIdx.x;
    const int lane = tid & 31;
    const int wid = tid >> 5;
    const int warp_m = wid & 1;         // 2 row-warps
    const int warp_n = wid >> 1;        // 4 col-warps
    const int bm = blockIdx.y * GBM;
    const int bn = blockIdx.x * GBN;

    float acc[4][4][4];
    #pragma unroll
    for (int mi = 0; mi < 4; mi++)
        #pragma unroll
        for (int ni = 0; ni < 4; ni++)
            #pragma unroll
            for (int e = 0; e < 4; e++) acc[mi][ni][e] = 0.0f;

    const int nch = K / GBK;            // 16

    // stage loader: 4 tiles x 512 x 16B chunks / 256 threads
    auto load_stage = [&](int ch, int s) {
        const int k0 = ch * GBK;
        const __nv_bfloat16* srcs[4] = {Ah, Al, Bh, Bl};
        const int gb[4] = {bm, bm, bn, bn};
        const uint32_t doff[4] = {SM_AH, SM_AL, SM_BH, SM_BL};
        #pragma unroll
        for (int t = 0; t < 4; t++) {
            #pragma unroll
            for (int i = 0; i < 2; i++) {
                int u = tid + i * 256;
                int row = u >> 2, c = u & 3;
                const void* src = srcs[t] + (size_t)(gb[t] + row) * K + k0 + c * 8;
                uint32_t dst = sbase + s * STAGEB + doff[t] + row * ROWB + c * 16;
                CP_ASYNC16(dst, src);
            }
        }
        CP_COMMIT();
    };

    load_stage(0, 0);

    for (int ch = 0; ch < nch; ch++) {
        if (ch + 1 < nch) {
            load_stage(ch + 1, (ch + 1) & 1);
            CP_WAIT(1);
        } else {
            CP_WAIT(0);
        }
        __syncthreads();

        const uint32_t st = sbase + (ch & 1) * STAGEB;
        #pragma unroll
        for (int kk = 0; kk < 2; kk++) {
            uint32_t a_h[4][4], a_l[4][4], b_h[2][4], b_l[2][4];
            const int ar = lane & 15;
            const int ac = kk * 16 + ((lane >> 4) << 3);
            #pragma unroll
            for (int mi = 0; mi < 4; mi++) {
                uint32_t off = (uint32_t)((warp_m * 64 + mi * 16 + ar) * ROWB + ac * 2);
                ldmx4(a_h[mi], st + SM_AH + off);
                ldmx4(a_l[mi], st + SM_AL + off);
            }
            const int br = (lane & 7) + ((lane >> 4) << 3);
            const int bc = kk * 16 + (((lane >> 3) & 1) << 3);
            #pragma unroll
            for (int nb = 0; nb < 2; nb++) {
                uint32_t off = (uint32_t)((warp_n * 32 + nb * 16 + br) * ROWB + bc * 2);
                ldmx4(b_h[nb], st + SM_BH + off);
                ldmx4(b_l[nb], st + SM_BL + off);
            }
            #pragma unroll
            for (int mi = 0; mi < 4; mi++) {
                #pragma unroll
                for (int ni = 0; ni < 4; ni++) {
                    const int nb = ni >> 1, hf = (ni & 1) * 2;
                    uint32_t bh2[2] = {b_h[nb][hf], b_h[nb][hf + 1]};
                    uint32_t bl2[2] = {b_l[nb][hf], b_l[nb][hf + 1]};
                    mma16816(acc[mi][ni], a_h[mi], bh2);
                    mma16816(acc[mi][ni], a_h[mi], bl2);
                    mma16816(acc[mi][ni], a_l[mi], bh2);
                }
            }
        }
        __syncthreads();
    }

    // Epilogue: bias + fp32 store (float2 per fragment row)
    const int tr = lane >> 2;
    const int tc = (lane & 3) * 2;
    #pragma unroll
    for (int mi = 0; mi < 4; mi++) {
        const int r0 = bm + warp_m * 64 + mi * 16 + tr;
        #pragma unroll
        for (int ni = 0; ni < 4; ni++) {
            const int col = bn + warp_n * 32 + ni * 8 + tc;
            const float b0 = __ldg(&bias[col]);
            const float b1 = __ldg(&bias[col + 1]);
            float2 v0 = make_float2(acc[mi][ni][0] + b0, acc[mi][ni][1] + b1);
            float2 v1 = make_float2(acc[mi][ni][2] + b0, acc[mi][ni][3] + b1);
            *(float2*)(C + (size_t)r0 * N + col) = v0;
            *(float2*)(C + (size_t)(r0 + 8) * N + col) = v1;
        }
    }
}

// ---------------------------------------------------------------------------
// Attention: one block per (window b, head h). 256 threads.
// Now writes ctx as bf16 hi/lo for the downstream mma GEMM.
// ---------------------------------------------------------------------------
__global__ __launch_bounds__(256) void attn_kernel(
    const float* __restrict__ bias_table,
    const int*   __restrict__ rel_index,
    const float* __restrict__ mask)
{
    __shared__ float qs[LTOK * 32];
    __shared__ float ks[LTOK * 33];
    __shared__ float vs[LTOK * 32];
    __shared__ float sc[LTOK * LTOK];

    const int bh = blockIdx.x;
    const int b = bh >> 4;
    const int h = bh & 15;
    const int w = bh & (NMASK - 1);
    const int tid = threadIdx.x;
    const float scale = 0.17677669529663687f;

    for (int t = tid; t < LTOK * 32; t += 256) {
        int l = t >> 5, c = t & 31;
        size_t base = ((size_t)(b * LTOK + l)) * N_QKV + h * HDIM + c;
        qs[l * 32 + c] = g_qkv[base] * scale;
        ks[l * 33 + c] = g_qkv[base + DMODEL];
        vs[l * 32 + c] = g_qkv[base + 2 * DMODEL];
    }
    __syncthreads();

    const float* mrow = mask + (size_t)w * LTOK * LTOK;
    for (int idx = tid; idx < LTOK * LTOK; idx += 256) {
        int i = idx / LTOK, j = idx - i * LTOK;
        float s = 0.0f;
        #pragma unroll
        for (int kk = 0; kk < 32; kk++)
            s = fmaf(qs[i * 32 + kk], ks[j * 33 + kk], s);
        int ri = __ldg(&rel_index[idx]);
        s += __ldg(&bias_table[ri * NHEAD + h]);
        s += __ldg(&mrow[idx]);
        sc[idx] = s;
    }
    __syncthreads();

    const int warp = tid >> 5, lane = tid & 31;
    for (int i = warp; i < LTOK; i += 8) {
        float m = -1e30f;
        for (int j = lane; j < LTOK; j += 32) m = fmaxf(m, sc[i * LTOK + j]);
        #pragma unroll
        for (int o = 16; o; o >>= 1) m = fmaxf(m, __shfl_xor_sync(0xffffffffu, m, o));
        float sum = 0.0f;
        for (int j = lane; j < LTOK; j += 32) {
            float e = expf(sc[i * LTOK + j] - m);
            sc[i * LTOK + j] = e;
            sum += e;
        }
        #pragma unroll
        for (int o = 16; o; o >>= 1) sum += __shfl_xor_sync(0xffffffffu, sum, o);
        float inv = 1.0f / sum;
        for (int j = lane; j < LTOK; j += 32) sc[i * LTOK + j] *= inv;
    }
    __syncthreads();

    for (int idx = tid; idx < LTOK * 32; idx += 256) {
        int i = idx >> 5, c = idx & 31;
        float acc = 0.0f;
        #pragma unroll 7
        for (int j = 0; j < LTOK; j++)
            acc = fmaf(sc[i * LTOK + j], vs[j * 32 + c], acc);
        size_t gi = ((size_t)(b * LTOK + i)) * DMODEL + h * HDIM + c;
        __nv_bfloat16 hi = __float2bfloat16(acc);
        g_ctx_hi[gi] = hi;
        g_ctx_lo[gi] = __float2bfloat16(acc - __bfloat162float(hi));
    }
}

// ---------------------------------------------------------------------------
// Launch
// ---------------------------------------------------------------------------
extern "C" void kernel_launch(void* const* d_in, const int* in_sizes, int n_in,
                              void* d_out, int out_size)
{
    const float* x          = (const float*)d_in[0];
    const float* w_qkv      = (const float*)d_in[1];
    const float* b_qkv      = (const float*)d_in[2];
    const float* w_out      = (const float*)d_in[3];
    const float* b_out      = (const float*)d_in[4];
    const float* bias_table = (const float*)d_in[5];
    const float* mask       = (const float*)d_in[6];
    const int*   rel_index  = (const int*)d_in[7];
    float*       out        = (float*)d_out;

    float* qkv_ptr = nullptr;
    __nv_bfloat16 *xh, *xl, *ch, *cl, *wqh, *wql, *woh, *wol;
    cudaGetSymbolAddress((void**)&qkv_ptr, g_qkv);
    cudaGetSymbolAddress((void**)&xh, g_x_hi);
    cudaGetSymbolAddress((void**)&xl, g_x_lo);
    cudaGetSymbolAddress((void**)&ch, g_ctx_hi);
    cudaGetSymbolAddress((void**)&cl, g_ctx_lo);
    cudaGetSymbolAddress((void**)&wqh, g_wqkvT_hi);
    cudaGetSymbolAddress((void**)&wql, g_wqkvT_lo);
    cudaGetSymbolAddress((void**)&woh, g_woutT_hi);
    cudaGetSymbolAddress((void**)&wol, g_woutT_lo);

    static bool attr_set = false;
    if (!attr_set) {
        cudaFuncSetAttribute(gemm_mma, cudaFuncAttributeMaxDynamicSharedMemorySize, SM_TOTAL);
        attr_set = true;
    }

    // Prep: split x + weights into bf16 hi/lo
    int n4 = MROWS * DMODEL / 4;
    prep_split_x<<<(n4 + 255) / 256, 256>>>(x, xh, xl, n4);
    prep_split_w<<<(N_QKV * DMODEL + 255) / 256, 256>>>(w_qkv, wqh, wql, DMODEL, N_QKV);
    prep_split_w<<<(DMODEL * DMODEL + 255) / 256, 256>>>(w_out, woh, wol, DMODEL, DMODEL);

    // QKV projection: [100352,512] @ [512,1536] + b_qkv
    dim3 g1(N_QKV / GBN, MROWS / GBM);
    gemm_mma<<<g1, 256, SM_TOTAL>>>(xh, xl, wqh, wql, b_qkv, qkv_ptr, MROWS, N_QKV, DMODEL);

    // Attention per (window, head)
    attn_kernel<<<BS * NHEAD, 256>>>(bias_table, rel_index, mask);

    // Output projection: [100352,512] @ [512,512] + b_out
    dim3 g2(DMODEL / GBN, MROWS / GBM);
    gemm_mma<<<g2, 256, SM_TOTAL>>>(ch, cl, woh, wol, b_out, out, MROWS, DMODEL, DMODEL);
}

// round 4
// speedup vs baseline: 2.1927x; 1.1457x over previous
#include <cuda_runtime.h>
#include <cuda_bf16.h>
#include <math.h>
#include <stdint.h>

// Problem constants
#define BS     2048
#define LTOK   49
#define DMODEL 512
#define NHEAD  16
#define HDIM   32
#define NMASK  64
#define MROWS  (BS * LTOK)          // 100352
#define N_QKV  (3 * DMODEL)         // 1536
#define LL     (LTOK * LTOK)        // 2401

// Scratch (device globals: allocation-free per harness rules)
__device__ float g_qkv[(size_t)MROWS * N_QKV];            // [100352, 1536] f32
__device__ __nv_bfloat16 g_x_hi[(size_t)MROWS * DMODEL];
__device__ __nv_bfloat16 g_x_lo[(size_t)MROWS * DMODEL];
__device__ __nv_bfloat16 g_ctx_hi[(size_t)MROWS * DMODEL];
__device__ __nv_bfloat16 g_ctx_lo[(size_t)MROWS * DMODEL];
__device__ __nv_bfloat16 g_wqkvT_hi[(size_t)N_QKV * DMODEL];
__device__ __nv_bfloat16 g_wqkvT_lo[(size_t)N_QKV * DMODEL];
__device__ __nv_bfloat16 g_woutT_hi[(size_t)DMODEL * DMODEL];
__device__ __nv_bfloat16 g_woutT_lo[(size_t)DMODEL * DMODEL];
__device__ float g_fbias[NHEAD * LL];                      // fused rel-pos bias [H][L*L]

// ---------------------------------------------------------------------------
// PTX helpers (sm_80-compatible: cp.async + ldmatrix + mma.sync only)
// ---------------------------------------------------------------------------
__device__ __forceinline__ uint32_t smem_u32(const void* p) {
    uint32_t a;
    asm("{ .reg .u64 t; cvta.to.shared.u64 t, %1; cvt.u32.u64 %0, t; }" : "=r"(a) : "l"(p));
    return a;
}
#define CP_ASYNC16(dst, src) \
    asm volatile("cp.async.cg.shared.global [%0], [%1], 16;" :: "r"(dst), "l"(src))
#define CP_COMMIT() asm volatile("cp.async.commit_group;" ::: "memory")
#define CP_WAIT(n)  asm volatile("cp.async.wait_group %0;" :: "n"(n) : "memory")

__device__ __forceinline__ void ldmx4(uint32_t* r, uint32_t addr) {
    asm volatile("ldmatrix.sync.aligned.m8n8.x4.shared.b16 {%0,%1,%2,%3}, [%4];"
                 : "=r"(r[0]), "=r"(r[1]), "=r"(r[2]), "=r"(r[3]) : "r"(addr));
}
__device__ __forceinline__ void mma16816(float* d, const uint32_t* a, const uint32_t* b) {
    asm volatile(
        "mma.sync.aligned.m16n8k16.row.col.f32.bf16.bf16.f32 "
        "{%0,%1,%2,%3}, {%4,%5,%6,%7}, {%8,%9}, {%0,%1,%2,%3};"
        : "+f"(d[0]), "+f"(d[1]), "+f"(d[2]), "+f"(d[3])
        : "r"(a[0]), "r"(a[1]), "r"(a[2]), "r"(a[3]), "r"(b[0]), "r"(b[1]));
}

// SW64 swizzle for 64-byte smem rows: conflict-free ldmatrix + cp.async
__device__ __forceinline__ uint32_t sw64(int row, int bytecol) {
    return (uint32_t)(row * 64 + (bytecol ^ ((row & 6) << 3)));
}

// ---------------------------------------------------------------------------
// Prep kernels
// ---------------------------------------------------------------------------
__global__ void prep_split_x(const float* __restrict__ x,
                             __nv_bfloat16* __restrict__ hi,
                             __nv_bfloat16* __restrict__ lo, int n4)
{
    int i = blockIdx.x * blockDim.x + threadIdx.x;
    if (i >= n4) return;
    float4 v = ((const float4*)x)[i];
    __nv_bfloat162 h01 = __floats2bfloat162_rn(v.x, v.y);
    __nv_bfloat162 h23 = __floats2bfloat162_rn(v.z, v.w);
    __nv_bfloat162 l01 = __floats2bfloat162_rn(v.x - __bfloat162float(h01.x),
                                               v.y - __bfloat162float(h01.y));
    __nv_bfloat162 l23 = __floats2bfloat162_rn(v.z - __bfloat162float(h23.x),
                                               v.w - __bfloat162float(h23.y));
    ((__nv_bfloat162*)hi)[i * 2 + 0] = h01;
    ((__nv_bfloat162*)hi)[i * 2 + 1] = h23;
    ((__nv_bfloat162*)lo)[i * 2 + 0] = l01;
    ((__nv_bfloat162*)lo)[i * 2 + 1] = l23;
}

__global__ void prep_split_w(const float* __restrict__ W,
                             __nv_bfloat16* __restrict__ Wt_hi,
                             __nv_bfloat16* __restrict__ Wt_lo,
                             int K, int N)
{
    int idx = blockIdx.x * blockDim.x + threadIdx.x;   // n*K + k
    if (idx >= K * N) return;
    int n = idx / K, k = idx - n * K;
    float w = W[(size_t)k * N + n];
    __nv_bfloat16 hi = __float2bfloat16(w);
    Wt_hi[idx] = hi;
    Wt_lo[idx] = __float2bfloat16(w - __bfloat162float(hi));
}

// Fuse rel-pos bias gather into dense [H][L*L]
__global__ void prep_bias(const float* __restrict__ bias_table,
                          const int* __restrict__ rel_index)
{
    int i = blockIdx.x * blockDim.x + threadIdx.x;
    if (i >= NHEAD * LL) return;
    int h = i / LL, idx = i - h * LL;
    g_fbias[i] = bias_table[rel_index[idx] * NHEAD + h];
}

// ---------------------------------------------------------------------------
// mma.sync GEMM: C[M,N] = (Ah+Al)[M,K] @ (Bh+Bl)[N,K]^T + bias (fp32 acc)
// 3-term split. 128x128 tile, BK=32, 8 warps (64x32 warp tile),
// 3-stage cp.async pipeline, SW64-swizzled 64B smem rows, 1 sync/chunk.
// ---------------------------------------------------------------------------
#define GBM 128
#define GBN 128
#define GBK 32
#define TILEB (128 * 64)                // 8192
#define STAGEB (4 * TILEB)              // 32768
#define NSTAGE 3
#define SM_AH 0
#define SM_AL TILEB
#define SM_BH (2 * TILEB)
#define SM_BL (3 * TILEB)
#define SM_TOTAL (NSTAGE * STAGEB)      // 98304

__global__ __launch_bounds__(256, 2) void gemm_mma(
    const __nv_bfloat16* __restrict__ Ah, const __nv_bfloat16* __restrict__ Al,
    const __nv_bfloat16* __restrict__ Bh, const __nv_bfloat16* __restrict__ Bl,
    const float* __restrict__ bias, float* __restrict__ C,
    int M, int N, int K)
{
    extern __shared__ char smem[];
    const uint32_t sbase = smem_u32(smem);
    const int tid = threadIdx.x;
    const int lane = tid & 31;
    const int wid = tid >> 5;
    const int warp_m = wid & 1;         // 2 row-warps (64 rows each)
    const int warp_n = wid >> 1;        // 4 col-warps (32 cols each)
    const int bm = blockIdx.y * GBM;
    const int bn = blockIdx.x * GBN;

    float acc[4][4][4];
    #pragma unroll
    for (int mi = 0; mi < 4; mi++)
        #pragma unroll
        for (int ni = 0; ni < 4; ni++)
            #pragma unroll
            for (int e = 0; e < 4; e++) acc[mi][ni][e] = 0.0f;

    const int nch = K / GBK;            // 16

    // stage loader: 4 tiles x 512 x 16B chunks / 256 threads = 8 cp.async/thread
    auto load_stage = [&](int ch, int s) {
        const int k0 = ch * GBK;
        const __nv_bfloat16* srcs[4] = {Ah, Al, Bh, Bl};
        const int gb[4] = {bm, bm, bn, bn};
        const uint32_t doff[4] = {SM_AH, SM_AL, SM_BH, SM_BL};
        const uint32_t stbase = sbase + (uint32_t)s * STAGEB;
        #pragma unroll
        for (int t = 0; t < 4; t++) {
            #pragma unroll
            for (int i = 0; i < 2; i++) {
                int u = tid + i * 256;
                int row = u >> 2, c = u & 3;
                const void* src = srcs[t] + (size_t)(gb[t] + row) * K + k0 + c * 8;
                uint32_t dst = stbase + doff[t] + sw64(row, c * 16);
                CP_ASYNC16(dst, src);
            }
        }
        CP_COMMIT();
    };

    load_stage(0, 0);
    load_stage(1, 1);

    int slot = 0;
    for (int ch = 0; ch < nch; ch++) {
        if (ch + 1 < nch) { CP_WAIT(1); } else { CP_WAIT(0); }
        __syncthreads();   // all warps done with slot (ch+2)%3 from chunk ch-1
        if (ch + 2 < nch) load_stage(ch + 2, (slot + 2) % NSTAGE);

        const uint32_t st = sbase + (uint32_t)slot * STAGEB;
        #pragma unroll
        for (int kk = 0; kk < 2; kk++) {
            uint32_t a_h[4][4], a_l[4][4], b_h[2][4], b_l[2][4];
            const int ar = lane & 15;
            const int abyte = kk * 32 + ((lane >> 4) << 4);
            #pragma unroll
            for (int mi = 0; mi < 4; mi++) {
                uint32_t off = sw64(warp_m * 64 + mi * 16 + ar, abyte);
                ldmx4(a_h[mi], st + SM_AH + off);
                ldmx4(a_l[mi], st + SM_AL + off);
            }
            const int br = (lane & 7) + ((lane >> 4) << 3);
            const int bbyte = kk * 32 + (((lane >> 3) & 1) << 4);
            #pragma unroll
            for (int nb = 0; nb < 2; nb++) {
                uint32_t off = sw64(warp_n * 32 + nb * 16 + br, bbyte);
                ldmx4(b_h[nb], st + SM_BH + off);
                ldmx4(b_l[nb], st + SM_BL + off);
            }
            #pragma unroll
            for (int mi = 0; mi < 4; mi++) {
                #pragma unroll
                for (int ni = 0; ni < 4; ni++) {
                    const int nb = ni >> 1, hf = (ni & 1) * 2;
                    uint32_t bh2[2] = {b_h[nb][hf], b_h[nb][hf + 1]};
                    uint32_t bl2[2] = {b_l[nb][hf], b_l[nb][hf + 1]};
                    mma16816(acc[mi][ni], a_h[mi], bh2);
                    mma16816(acc[mi][ni], a_h[mi], bl2);
                    mma16816(acc[mi][ni], a_l[mi], bh2);
                }
            }
        }
        slot = (slot + 1) % NSTAGE;
    }

    // Epilogue: bias + fp32 store
    const int tr = lane >> 2;
    const int tc = (lane & 3) * 2;
    #pragma unroll
    for (int mi = 0; mi < 4; mi++) {
        const int r0 = bm + warp_m * 64 + mi * 16 + tr;
        #pragma unroll
        for (int ni = 0; ni < 4; ni++) {
            const int col = bn + warp_n * 32 + ni * 8 + tc;
            const float b0 = __ldg(&bias[col]);
            const float b1 = __ldg(&bias[col + 1]);
            float2 v0 = make_float2(acc[mi][ni][0] + b0, acc[mi][ni][1] + b1);
            float2 v1 = make_float2(acc[mi][ni][2] + b0, acc[mi][ni][3] + b1);
            *(float2*)(C + (size_t)r0 * N + col) = v0;
            *(float2*)(C + (size_t)(r0 + 8) * N + col) = v1;
        }
    }
}

// ---------------------------------------------------------------------------
// Attention: one block per (window b, head h). 256 threads.
// __expf + pre-fused bias table; writes ctx as bf16 hi/lo.
// ---------------------------------------------------------------------------
__global__ __launch_bounds__(256) void attn_kernel(const float* __restrict__ mask)
{
    __shared__ float qs[LTOK * 32];
    __shared__ float ks[LTOK * 33];
    __shared__ float vs[LTOK * 32];
    __shared__ float sc[LL];

    const int bh = blockIdx.x;
    const int b = bh >> 4;
    const int h = bh & 15;
    const int w = bh & (NMASK - 1);
    const int tid = threadIdx.x;
    const float scale = 0.17677669529663687f;

    for (int t = tid; t < LTOK * 32; t += 256) {
        int l = t >> 5, c = t & 31;
        size_t base = ((size_t)(b * LTOK + l)) * N_QKV + h * HDIM + c;
        qs[l * 32 + c] = g_qkv[base] * scale;
        ks[l * 33 + c] = g_qkv[base + DMODEL];
        vs[l * 32 + c] = g_qkv[base + 2 * DMODEL];
    }
    __syncthreads();

    const float* mrow = mask + (size_t)w * LL;
    const float* frow = g_fbias + (size_t)h * LL;
    for (int idx = tid; idx < LL; idx += 256) {
        int i = idx / LTOK, j = idx - i * LTOK;
        float s = 0.0f;
        #pragma unroll
        for (int kk = 0; kk < 32; kk++)
            s = fmaf(qs[i * 32 + kk], ks[j * 33 + kk], s);
        sc[idx] = s + __ldg(&frow[idx]) + __ldg(&mrow[idx]);
    }
    __syncthreads();

    const int warp = tid >> 5, lane = tid & 31;
    for (int i = warp; i < LTOK; i += 8) {
        float m = -1e30f;
        for (int j = lane; j < LTOK; j += 32) m = fmaxf(m, sc[i * LTOK + j]);
        #pragma unroll
        for (int o = 16; o; o >>= 1) m = fmaxf(m, __shfl_xor_sync(0xffffffffu, m, o));
        float sum = 0.0f;
        for (int j = lane; j < LTOK; j += 32) {
            float e = __expf(sc[i * LTOK + j] - m);
            sc[i * LTOK + j] = e;
            sum += e;
        }
        #pragma unroll
        for (int o = 16; o; o >>= 1) sum += __shfl_xor_sync(0xffffffffu, sum, o);
        float inv = 1.0f / sum;
        for (int j = lane; j < LTOK; j += 32) sc[i * LTOK + j] *= inv;
    }
    __syncthreads();

    for (int idx = tid; idx < LTOK * 32; idx += 256) {
        int i = idx >> 5, c = idx & 31;
        float acc = 0.0f;
        #pragma unroll 7
        for (int j = 0; j < LTOK; j++)
            acc = fmaf(sc[i * LTOK + j], vs[j * 32 + c], acc);
        size_t gi = ((size_t)(b * LTOK + i)) * DMODEL + h * HDIM + c;
        __nv_bfloat16 hi = __float2bfloat16(acc);
        g_ctx_hi[gi] = hi;
        g_ctx_lo[gi] = __float2bfloat16(acc - __bfloat162float(hi));
    }
}

// ---------------------------------------------------------------------------
// Launch
// ---------------------------------------------------------------------------
extern "C" void kernel_launch(void* const* d_in, const int* in_sizes, int n_in,
                              void* d_out, int out_size)
{
    const float* x          = (const float*)d_in[0];
    const float* w_qkv      = (const float*)d_in[1];
    const float* b_qkv      = (const float*)d_in[2];
    const float* w_out      = (const float*)d_in[3];
    const float* b_out      = (const float*)d_in[4];
    const float* bias_table = (const float*)d_in[5];
    const float* mask       = (const float*)d_in[6];
    const int*   rel_index  = (const int*)d_in[7];
    float*       out        = (float*)d_out;

    float* qkv_ptr = nullptr;
    __nv_bfloat16 *xh, *xl, *ch, *cl, *wqh, *wql, *woh, *wol;
    cudaGetSymbolAddress((void**)&qkv_ptr, g_qkv);
    cudaGetSymbolAddress((void**)&xh, g_x_hi);
    cudaGetSymbolAddress((void**)&xl, g_x_lo);
    cudaGetSymbolAddress((void**)&ch, g_ctx_hi);
    cudaGetSymbolAddress((void**)&cl, g_ctx_lo);
    cudaGetSymbolAddress((void**)&wqh, g_wqkvT_hi);
    cudaGetSymbolAddress((void**)&wql, g_wqkvT_lo);
    cudaGetSymbolAddress((void**)&woh, g_woutT_hi);
    cudaGetSymbolAddress((void**)&wol, g_woutT_lo);

    static bool attr_set = false;
    if (!attr_set) {
        cudaFuncSetAttribute(gemm_mma, cudaFuncAttributeMaxDynamicSharedMemorySize, SM_TOTAL);
        attr_set = true;
    }

    // Prep: split inputs/weights, fuse bias table
    int n4 = MROWS * DMODEL / 4;
    prep_split_x<<<(n4 + 255) / 256, 256>>>(x, xh, xl, n4);
    prep_split_w<<<(N_QKV * DMODEL + 255) / 256, 256>>>(w_qkv, wqh, wql, DMODEL, N_QKV);
    prep_split_w<<<(DMODEL * DMODEL + 255) / 256, 256>>>(w_out, woh, wol, DMODEL, DMODEL);
    prep_bias<<<(NHEAD * LL + 255) / 256, 256>>>(bias_table, rel_index);

    // QKV projection
    dim3 g1(N_QKV / GBN, MROWS / GBM);
    gemm_mma<<<g1, 256, SM_TOTAL>>>(xh, xl, wqh, wql, b_qkv, qkv_ptr, MROWS, N_QKV, DMODEL);

    // Attention
    attn_kernel<<<BS * NHEAD, 256>>>(mask);

    // Output projection
    dim3 g2(DMODEL / GBN, MROWS / GBM);
    gemm_mma<<<g2, 256, SM_TOTAL>>>(ch, cl, woh, wol, b_out, out, MROWS, DMODEL, DMODEL);
}

// round 5
// speedup vs baseline: 3.0869x; 1.4078x over previous
#include <cuda_runtime.h>
#include <cuda_fp16.h>
#include <math.h>
#include <stdint.h>

// Problem constants
#define BS     2048
#define LTOK   49
#define DMODEL 512
#define NHEAD  16
#define HDIM   32
#define NMASK  64
#define MROWS  (BS * LTOK)          // 100352
#define N_QKV  (3 * DMODEL)         // 1536
#define LL     (LTOK * LTOK)        // 2401

// Scratch (device globals: allocation-free per harness rules)
__device__ float g_qkv[(size_t)MROWS * N_QKV];            // [100352, 1536] f32
__device__ __half g_x_h[(size_t)MROWS * DMODEL];          // x as fp16
__device__ __half g_ctx_h[(size_t)MROWS * DMODEL];        // ctx as fp16
__device__ __half g_wqkvT_h[(size_t)N_QKV * DMODEL];      // W^T [N,K] fp16
__device__ __half g_woutT_h[(size_t)DMODEL * DMODEL];
__device__ float g_fbias[NHEAD * LL];                     // fused rel-pos bias [H][L*L]

// ---------------------------------------------------------------------------
// PTX helpers (sm_80-compatible: cp.async + ldmatrix + mma.sync only)
// ---------------------------------------------------------------------------
__device__ __forceinline__ uint32_t smem_u32(const void* p) {
    uint32_t a;
    asm("{ .reg .u64 t; cvta.to.shared.u64 t, %1; cvt.u32.u64 %0, t; }" : "=r"(a) : "l"(p));
    return a;
}
#define CP_ASYNC16(dst, src) \
    asm volatile("cp.async.cg.shared.global [%0], [%1], 16;" :: "r"(dst), "l"(src))
#define CP_COMMIT() asm volatile("cp.async.commit_group;" ::: "memory")
#define CP_WAIT(n)  asm volatile("cp.async.wait_group %0;" :: "n"(n) : "memory")

__device__ __forceinline__ void ldmx4(uint32_t* r, uint32_t addr) {
    asm volatile("ldmatrix.sync.aligned.m8n8.x4.shared.b16 {%0,%1,%2,%3}, [%4];"
                 : "=r"(r[0]), "=r"(r[1]), "=r"(r[2]), "=r"(r[3]) : "r"(addr));
}
__device__ __forceinline__ void mma16816(float* d, const uint32_t* a, const uint32_t* b) {
    asm volatile(
        "mma.sync.aligned.m16n8k16.row.col.f32.f16.f16.f32 "
        "{%0,%1,%2,%3}, {%4,%5,%6,%7}, {%8,%9}, {%0,%1,%2,%3};"
        : "+f"(d[0]), "+f"(d[1]), "+f"(d[2]), "+f"(d[3])
        : "r"(a[0]), "r"(a[1]), "r"(a[2]), "r"(a[3]), "r"(b[0]), "r"(b[1]));
}

// SW64 swizzle for 64-byte smem rows: conflict-free ldmatrix + cp.async
__device__ __forceinline__ uint32_t sw64(int row, int bytecol) {
    return (uint32_t)(row * 64 + (bytecol ^ ((row & 6) << 3)));
}

// ---------------------------------------------------------------------------
// Prep kernels
// ---------------------------------------------------------------------------
__global__ void prep_half_x(const float* __restrict__ x,
                            __half* __restrict__ out, int n4)
{
    int i = blockIdx.x * blockDim.x + threadIdx.x;
    if (i >= n4) return;
    float4 v = ((const float4*)x)[i];
    __half2 h01 = __floats2half2_rn(v.x, v.y);
    __half2 h23 = __floats2half2_rn(v.z, v.w);
    ((__half2*)out)[i * 2 + 0] = h01;
    ((__half2*)out)[i * 2 + 1] = h23;
}

__global__ void prep_half_wT(const float* __restrict__ W,
                             __half* __restrict__ Wt, int K, int N)
{
    int idx = blockIdx.x * blockDim.x + threadIdx.x;   // n*K + k
    if (idx >= K * N) return;
    int n = idx / K, k = idx - n * K;
    Wt[idx] = __float2half_rn(W[(size_t)k * N + n]);
}

// Fuse rel-pos bias gather into dense [H][L*L]
__global__ void prep_bias(const float* __restrict__ bias_table,
                          const int* __restrict__ rel_index)
{
    int i = blockIdx.x * blockDim.x + threadIdx.x;
    if (i >= NHEAD * LL) return;
    int h = i / LL, idx = i - h * LL;
    g_fbias[i] = bias_table[rel_index[idx] * NHEAD + h];
}

// ---------------------------------------------------------------------------
// mma.sync GEMM: C[M,N] = A[M,K](fp16) @ B[N,K](fp16)^T + bias (fp32 acc)
// 128x128 tile, BK=32, 8 warps (64x32 warp tile),
// 5-stage cp.async pipeline, SW64-swizzled 64B smem rows, 1 sync/chunk.
// ---------------------------------------------------------------------------
#define GBM 128
#define GBN 128
#define GBK 32
#define TILEB (128 * 64)                // 8192
#define STAGEB (2 * TILEB)              // 16384 (A + B)
#define NSTAGE 5
#define SM_A 0
#define SM_B TILEB
#define SM_TOTAL (NSTAGE * STAGEB)      // 81920

__global__ __launch_bounds__(256, 2) void gemm_mma(
    const __half* __restrict__ A, const __half* __restrict__ B,
    const float* __restrict__ bias, float* __restrict__ C,
    int M, int N, int K)
{
    extern __shared__ char smem[];
    const uint32_t sbase = smem_u32(smem);
    const int tid = threadIdx.x;
    const int lane = tid & 31;
    const int wid = tid >> 5;
    const int warp_m = wid & 1;         // 2 row-warps (64 rows each)
    const int warp_n = wid >> 1;        // 4 col-warps (32 cols each)
    const int bm = blockIdx.y * GBM;
    const int bn = blockIdx.x * GBN;

    float acc[4][4][4];
    #pragma unroll
    for (int mi = 0; mi < 4; mi++)
        #pragma unroll
        for (int ni = 0; ni < 4; ni++)
            #pragma unroll
            for (int e = 0; e < 4; e++) acc[mi][ni][e] = 0.0f;

    const int nch = K / GBK;            // 16

    // stage loader: 2 tiles x 512 x 16B chunks / 256 threads = 4 cp.async/thread
    auto load_stage = [&](int ch, int s) {
        const int k0 = ch * GBK;
        const uint32_t stbase = sbase + (uint32_t)s * STAGEB;
        #pragma unroll
        for (int i = 0; i < 2; i++) {
            int u = tid + i * 256;
            int row = u >> 2, c = u & 3;
            const void* srcA = A + (size_t)(bm + row) * K + k0 + c * 8;
            CP_ASYNC16(stbase + SM_A + sw64(row, c * 16), srcA);
            const void* srcB = B + (size_t)(bn + row) * K + k0 + c * 8;
            CP_ASYNC16(stbase + SM_B + sw64(row, c * 16), srcB);
        }
        CP_COMMIT();
    };

    // Prologue: fill 4 stages ahead
    load_stage(0, 0);
    load_stage(1, 1);
    load_stage(2, 2);
    load_stage(3, 3);

    int slot = 0;
    for (int ch = 0; ch < nch; ch++) {
        if (ch + 3 < nch)      { CP_WAIT(3); }
        else if (ch + 2 < nch) { CP_WAIT(2); }
        else if (ch + 1 < nch) { CP_WAIT(1); }
        else                   { CP_WAIT(0); }
        __syncthreads();   // slot (ch+4)%5 fully consumed (chunk ch-1 done last iter)
        if (ch + 4 < nch) load_stage(ch + 4, (slot + 4) % NSTAGE);

        const uint32_t st = sbase + (uint32_t)slot * STAGEB;
        #pragma unroll
        for (int kk = 0; kk < 2; kk++) {
            uint32_t a_f[4][4], b_f[2][4];
            const int ar = lane & 15;
            const int abyte = kk * 32 + ((lane >> 4) << 4);
            #pragma unroll
            for (int mi = 0; mi < 4; mi++)
                ldmx4(a_f[mi], st + SM_A + sw64(warp_m * 64 + mi * 16 + ar, abyte));
            const int br = (lane & 7) + ((lane >> 4) << 3);
            const int bbyte = kk * 32 + (((lane >> 3) & 1) << 4);
            #pragma unroll
            for (int nb = 0; nb < 2; nb++)
                ldmx4(b_f[nb], st + SM_B + sw64(warp_n * 32 + nb * 16 + br, bbyte));
            #pragma unroll
            for (int mi = 0; mi < 4; mi++) {
                #pragma unroll
                for (int ni = 0; ni < 4; ni++) {
                    const int nb = ni >> 1, hf = (ni & 1) * 2;
                    uint32_t b2[2] = {b_f[nb][hf], b_f[nb][hf + 1]};
                    mma16816(acc[mi][ni], a_f[mi], b2);
                }
            }
        }
        slot = (slot + 1) % NSTAGE;
    }

    // Epilogue: bias + fp32 store
    const int tr = lane >> 2;
    const int tc = (lane & 3) * 2;
    #pragma unroll
    for (int mi = 0; mi < 4; mi++) {
        const int r0 = bm + warp_m * 64 + mi * 16 + tr;
        #pragma unroll
        for (int ni = 0; ni < 4; ni++) {
            const int col = bn + warp_n * 32 + ni * 8 + tc;
            const float b0 = __ldg(&bias[col]);
            const float b1 = __ldg(&bias[col + 1]);
            float2 v0 = make_float2(acc[mi][ni][0] + b0, acc[mi][ni][1] + b1);
            float2 v1 = make_float2(acc[mi][ni][2] + b0, acc[mi][ni][3] + b1);
            *(float2*)(C + (size_t)r0 * N + col) = v0;
            *(float2*)(C + (size_t)(r0 + 8) * N + col) = v1;
        }
    }
}

// ---------------------------------------------------------------------------
// Attention: one block per (window b, head h). 256 threads.
// Fully fp32 internally; writes ctx as fp16 for the downstream GEMM.
// ---------------------------------------------------------------------------
__global__ __launch_bounds__(256) void attn_kernel(const float* __restrict__ mask)
{
    __shared__ float qs[LTOK * 32];
    __shared__ float ks[LTOK * 33];
    __shared__ float vs[LTOK * 32];
    __shared__ float sc[LL];

    const int bh = blockIdx.x;
    const int b = bh >> 4;
    const int h = bh & 15;
    const int w = bh & (NMASK - 1);
    const int tid = threadIdx.x;
    const float scale = 0.17677669529663687f;

    for (int t = tid; t < LTOK * 32; t += 256) {
        int l = t >> 5, c = t & 31;
        size_t base = ((size_t)(b * LTOK + l)) * N_QKV + h * HDIM + c;
        qs[l * 32 + c] = g_qkv[base] * scale;
        ks[l * 33 + c] = g_qkv[base + DMODEL];
        vs[l * 32 + c] = g_qkv[base + 2 * DMODEL];
    }
    __syncthreads();

    const float* mrow = mask + (size_t)w * LL;
    const float* frow = g_fbias + (size_t)h * LL;
    for (int idx = tid; idx < LL; idx += 256) {
        int i = idx / LTOK, j = idx - i * LTOK;
        float s = 0.0f;
        #pragma unroll
        for (int kk = 0; kk < 32; kk++)
            s = fmaf(qs[i * 32 + kk], ks[j * 33 + kk], s);
        sc[idx] = s + __ldg(&frow[idx]) + __ldg(&mrow[idx]);
    }
    __syncthreads();

    const int warp = tid >> 5, lane = tid & 31;
    for (int i = warp; i < LTOK; i += 8) {
        float m = -1e30f;
        for (int j = lane; j < LTOK; j += 32) m = fmaxf(m, sc[i * LTOK + j]);
        #pragma unroll
        for (int o = 16; o; o >>= 1) m = fmaxf(m, __shfl_xor_sync(0xffffffffu, m, o));
        float sum = 0.0f;
        for (int j = lane; j < LTOK; j += 32) {
            float e = __expf(sc[i * LTOK + j] - m);
            sc[i * LTOK + j] = e;
            sum += e;
        }
        #pragma unroll
        for (int o = 16; o; o >>= 1) sum += __shfl_xor_sync(0xffffffffu, sum, o);
        float inv = 1.0f / sum;
        for (int j = lane; j < LTOK; j += 32) sc[i * LTOK + j] *= inv;
    }
    __syncthreads();

    for (int idx = tid; idx < LTOK * 32; idx += 256) {
        int i = idx >> 5, c = idx & 31;
        float acc = 0.0f;
        #pragma unroll 7
        for (int j = 0; j < LTOK; j++)
            acc = fmaf(sc[i * LTOK + j], vs[j * 32 + c], acc);
        size_t gi = ((size_t)(b * LTOK + i)) * DMODEL + h * HDIM + c;
        g_ctx_h[gi] = __float2half_rn(acc);
    }
}

// ---------------------------------------------------------------------------
// Launch
// ---------------------------------------------------------------------------
extern "C" void kernel_launch(void* const* d_in, const int* in_sizes, int n_in,
                              void* d_out, int out_size)
{
    const float* x          = (const float*)d_in[0];
    const float* w_qkv      = (const float*)d_in[1];
    const float* b_qkv      = (const float*)d_in[2];
    const float* w_out      = (const float*)d_in[3];
    const float* b_out      = (const float*)d_in[4];
    const float* bias_table = (const float*)d_in[5];
    const float* mask       = (const float*)d_in[6];
    const int*   rel_index  = (const int*)d_in[7];
    float*       out        = (float*)d_out;

    float* qkv_ptr = nullptr;
    __half *xh, *ch, *wqh, *woh;
    cudaGetSymbolAddress((void**)&qkv_ptr, g_qkv);
    cudaGetSymbolAddress((void**)&xh, g_x_h);
    cudaGetSymbolAddress((void**)&ch, g_ctx_h);
    cudaGetSymbolAddress((void**)&wqh, g_wqkvT_h);
    cudaGetSymbolAddress((void**)&woh, g_woutT_h);

    static bool attr_set = false;
    if (!attr_set) {
        cudaFuncSetAttribute(gemm_mma, cudaFuncAttributeMaxDynamicSharedMemorySize, SM_TOTAL);
        attr_set = true;
    }

    // Prep: fp16 conversions + fused bias table
    int n4 = MROWS * DMODEL / 4;
    prep_half_x<<<(n4 + 255) / 256, 256>>>(x, xh, n4);
    prep_half_wT<<<(N_QKV * DMODEL + 255) / 256, 256>>>(w_qkv, wqh, DMODEL, N_QKV);
    prep_half_wT<<<(DMODEL * DMODEL + 255) / 256, 256>>>(w_out, woh, DMODEL, DMODEL);
    prep_bias<<<(NHEAD * LL + 255) / 256, 256>>>(bias_table, rel_index);

    // QKV projection
    dim3 g1(N_QKV / GBN, MROWS / GBM);
    gemm_mma<<<g1, 256, SM_TOTAL>>>(xh, wqh, b_qkv, qkv_ptr, MROWS, N_QKV, DMODEL);

    // Attention
    attn_kernel<<<BS * NHEAD, 256>>>(mask);

    // Output projection
    dim3 g2(DMODEL / GBN, MROWS / GBM);
    gemm_mma<<<g2, 256, SM_TOTAL>>>(ch, woh, b_out, out, MROWS, DMODEL, DMODEL);
}

// round 6
// speedup vs baseline: 3.9580x; 1.2822x over previous
#include <cuda_runtime.h>
#include <cuda_fp16.h>
#include <math.h>
#include <stdint.h>

// Problem constants
#define BS     2048
#define LTOK   49
#define DMODEL 512
#define NHEAD  16
#define HDIM   32
#define NMASK  64
#define MROWS  (BS * LTOK)          // 100352
#define N_QKV  (3 * DMODEL)         // 1536
#define LL     (LTOK * LTOK)        // 2401

// Scratch (device globals: allocation-free per harness rules)
__device__ __half g_qkv_h[(size_t)MROWS * N_QKV];         // qkv as fp16
__device__ __half g_x_h[(size_t)MROWS * DMODEL];          // x as fp16
__device__ __half g_ctx_h[(size_t)MROWS * DMODEL];        // ctx as fp16
__device__ __half g_wqkvT_h[(size_t)N_QKV * DMODEL];      // W^T [N,K] fp16
__device__ __half g_woutT_h[(size_t)DMODEL * DMODEL];
__device__ float g_fbias[NHEAD * LL];                     // fused rel-pos bias [H][L*L]

// ---------------------------------------------------------------------------
// PTX helpers (sm_80-compatible: cp.async + ldmatrix + mma.sync only)
// ---------------------------------------------------------------------------
__device__ __forceinline__ uint32_t smem_u32(const void* p) {
    uint32_t a;
    asm("{ .reg .u64 t; cvta.to.shared.u64 t, %1; cvt.u32.u64 %0, t; }" : "=r"(a) : "l"(p));
    return a;
}
#define CP_ASYNC16(dst, src) \
    asm volatile("cp.async.cg.shared.global [%0], [%1], 16;" :: "r"(dst), "l"(src))
#define CP_COMMIT() asm volatile("cp.async.commit_group;" ::: "memory")
#define CP_WAIT(n)  asm volatile("cp.async.wait_group %0;" :: "n"(n) : "memory")

__device__ __forceinline__ void ldmx4(uint32_t* r, uint32_t addr) {
    asm volatile("ldmatrix.sync.aligned.m8n8.x4.shared.b16 {%0,%1,%2,%3}, [%4];"
                 : "=r"(r[0]), "=r"(r[1]), "=r"(r[2]), "=r"(r[3]) : "r"(addr));
}
__device__ __forceinline__ void mma16816(float* d, const uint32_t* a, const uint32_t* b) {
    asm volatile(
        "mma.sync.aligned.m16n8k16.row.col.f32.f16.f16.f32 "
        "{%0,%1,%2,%3}, {%4,%5,%6,%7}, {%8,%9}, {%0,%1,%2,%3};"
        : "+f"(d[0]), "+f"(d[1]), "+f"(d[2]), "+f"(d[3])
        : "r"(a[0]), "r"(a[1]), "r"(a[2]), "r"(a[3]), "r"(b[0]), "r"(b[1]));
}

// SW64 swizzle for 64-byte smem rows: conflict-free ldmatrix + cp.async
__device__ __forceinline__ uint32_t sw64(int row, int bytecol) {
    return (uint32_t)(row * 64 + (bytecol ^ ((row & 6) << 3)));
}

// ---------------------------------------------------------------------------
// Prep kernels
// ---------------------------------------------------------------------------
__global__ void prep_half_x(const float* __restrict__ x,
                            __half* __restrict__ out, int n4)
{
    int i = blockIdx.x * blockDim.x + threadIdx.x;
    if (i >= n4) return;
    float4 v = ((const float4*)x)[i];
    ((__half2*)out)[i * 2 + 0] = __floats2half2_rn(v.x, v.y);
    ((__half2*)out)[i * 2 + 1] = __floats2half2_rn(v.z, v.w);
}

__global__ void prep_half_wT(const float* __restrict__ W,
                             __half* __restrict__ Wt, int K, int N)
{
    int idx = blockIdx.x * blockDim.x + threadIdx.x;   // n*K + k
    if (idx >= K * N) return;
    int n = idx / K, k = idx - n * K;
    Wt[idx] = __float2half_rn(W[(size_t)k * N + n]);
}

__global__ void prep_bias(const float* __restrict__ bias_table,
                          const int* __restrict__ rel_index)
{
    int i = blockIdx.x * blockDim.x + threadIdx.x;
    if (i >= NHEAD * LL) return;
    int h = i / LL, idx = i - h * LL;
    g_fbias[i] = bias_table[rel_index[idx] * NHEAD + h];
}

// ---------------------------------------------------------------------------
// mma.sync GEMM: C[M,N] = A[M,K](fp16) @ B[N,K](fp16)^T + bias (fp32 acc)
// 128x128 tile, BK=32, 8 warps (64x32 warp tile), 5-stage cp.async pipeline.
// OutT = float or __half.
// ---------------------------------------------------------------------------
#define GBM 128
#define GBN 128
#define GBK 32
#define TILEB (128 * 64)                // 8192
#define STAGEB (2 * TILEB)              // 16384 (A + B)
#define NSTAGE 5
#define SM_A 0
#define SM_B TILEB
#define SM_TOTAL (NSTAGE * STAGEB)      // 81920

template <typename OutT>
__global__ __launch_bounds__(256, 2) void gemm_mma(
    const __half* __restrict__ A, const __half* __restrict__ B,
    const float* __restrict__ bias, OutT* __restrict__ C,
    int M, int N, int K)
{
    extern __shared__ char smem[];
    const uint32_t sbase = smem_u32(smem);
    const int tid = threadIdx.x;
    const int lane = tid & 31;
    const int wid = tid >> 5;
    const int warp_m = wid & 1;
    const int warp_n = wid >> 1;
    const int bm = blockIdx.y * GBM;
    const int bn = blockIdx.x * GBN;

    float acc[4][4][4];
    #pragma unroll
    for (int mi = 0; mi < 4; mi++)
        #pragma unroll
        for (int ni = 0; ni < 4; ni++)
            #pragma unroll
            for (int e = 0; e < 4; e++) acc[mi][ni][e] = 0.0f;

    const int nch = K / GBK;            // 16

    auto load_stage = [&](int ch, int s) {
        const int k0 = ch * GBK;
        const uint32_t stbase = sbase + (uint32_t)s * STAGEB;
        #pragma unroll
        for (int i = 0; i < 2; i++) {
            int u = tid + i * 256;
            int row = u >> 2, c = u & 3;
            const void* srcA = A + (size_t)(bm + row) * K + k0 + c * 8;
            CP_ASYNC16(stbase + SM_A + sw64(row, c * 16), srcA);
            const void* srcB = B + (size_t)(bn + row) * K + k0 + c * 8;
            CP_ASYNC16(stbase + SM_B + sw64(row, c * 16), srcB);
        }
        CP_COMMIT();
    };

    load_stage(0, 0);
    load_stage(1, 1);
    load_stage(2, 2);
    load_stage(3, 3);

    int slot = 0;
    for (int ch = 0; ch < nch; ch++) {
        if (ch + 3 < nch)      { CP_WAIT(3); }
        else if (ch + 2 < nch) { CP_WAIT(2); }
        else if (ch + 1 < nch) { CP_WAIT(1); }
        else                   { CP_WAIT(0); }
        __syncthreads();
        if (ch + 4 < nch) load_stage(ch + 4, (slot + 4) % NSTAGE);

        const uint32_t st = sbase + (uint32_t)slot * STAGEB;
        #pragma unroll
        for (int kk = 0; kk < 2; kk++) {
            uint32_t a_f[4][4], b_f[2][4];
            const int ar = lane & 15;
            const int abyte = kk * 32 + ((lane >> 4) << 4);
            #pragma unroll
            for (int mi = 0; mi < 4; mi++)
                ldmx4(a_f[mi], st + SM_A + sw64(warp_m * 64 + mi * 16 + ar, abyte));
            const int br = (lane & 7) + ((lane >> 4) << 3);
            const int bbyte = kk * 32 + (((lane >> 3) & 1) << 4);
            #pragma unroll
            for (int nb = 0; nb < 2; nb++)
                ldmx4(b_f[nb], st + SM_B + sw64(warp_n * 32 + nb * 16 + br, bbyte));
            #pragma unroll
            for (int mi = 0; mi < 4; mi++) {
                #pragma unroll
                for (int ni = 0; ni < 4; ni++) {
                    const int nb = ni >> 1, hf = (ni & 1) * 2;
                    uint32_t b2[2] = {b_f[nb][hf], b_f[nb][hf + 1]};
                    mma16816(acc[mi][ni], a_f[mi], b2);
                }
            }
        }
        slot = (slot + 1) % NSTAGE;
    }

    // Epilogue
    const int tr = lane >> 2;
    const int tc = (lane & 3) * 2;
    #pragma unroll
    for (int mi = 0; mi < 4; mi++) {
        const int r0 = bm + warp_m * 64 + mi * 16 + tr;
        #pragma unroll
        for (int ni = 0; ni < 4; ni++) {
            const int col = bn + warp_n * 32 + ni * 8 + tc;
            const float b0 = __ldg(&bias[col]);
            const float b1 = __ldg(&bias[col + 1]);
            float v00 = acc[mi][ni][0] + b0, v01 = acc[mi][ni][1] + b1;
            float v10 = acc[mi][ni][2] + b0, v11 = acc[mi][ni][3] + b1;
            if (sizeof(OutT) == 2) {
                *(__half2*)((__half*)C + (size_t)r0 * N + col) = __floats2half2_rn(v00, v01);
                *(__half2*)((__half*)C + (size_t)(r0 + 8) * N + col) = __floats2half2_rn(v10, v11);
            } else {
                *(float2*)((float*)C + (size_t)r0 * N + col) = make_float2(v00, v01);
                *(float2*)((float*)C + (size_t)(r0 + 8) * N + col) = make_float2(v10, v11);
            }
        }
    }
}

// ---------------------------------------------------------------------------
// Tensor-core attention: one block per (window b, head h), 128 threads (4 warps).
// S = Q K^T via mma (fp16 in, fp32 acc), softmax fp32, O = P V via mma.
// 49 padded to 64 rows/cols; padding kept inert via zeroed P cols / V rows.
// ---------------------------------------------------------------------------
#define TQK 40    // half stride for q/k rows (80 B, conflict-free ldmatrix)
#define SCW 66    // f32 stride for score rows (264 B)
#define TPV 72    // half stride for p/vt rows (144 B, conflict-free ldmatrix)

__global__ __launch_bounds__(128) void attn_tc(const float* __restrict__ mask)
{
    __shared__ __half qs[64 * TQK];
    __shared__ __half ks[64 * TQK];
    __shared__ __half vt[32 * TPV];     // V^T: [c][l]
    __shared__ float  sc[64 * SCW];
    __shared__ __half ph[64 * TPV];     // unnormalized exp(P), fp16
    __shared__ float  inv_s[64];

    const int bh = blockIdx.x;
    const int b = bh >> 4, h = bh & 15, w = bh & (NMASK - 1);
    const int tid = threadIdx.x, lane = tid & 31, wid = tid >> 5;
    const float scale = 0.17677669529663687f;   // 1/sqrt(32)

    // zero ph (padding rows/cols must stay zero)
    for (int i = tid; i < 64 * TPV / 2; i += 128)
        ((uint32_t*)ph)[i] = 0u;

    // load q, k (rows < 49; pad rows only feed unused S entries)
    const __half2* qkv2 = (const __half2*)g_qkv_h;
    for (int t = tid; t < 49 * 16; t += 128) {
        int l = t >> 4, c2 = t & 15;
        size_t base = (size_t)(b * LTOK + l) * 768 + h * 16 + c2;
        *(__half2*)&qs[l * TQK + c2 * 2] = qkv2[base];
        *(__half2*)&ks[l * TQK + c2 * 2] = qkv2[base + 256];
    }
    // v transposed with zero pad for l in [49,64)
    for (int t = tid; t < 64 * 16; t += 128) {
        int l = t >> 4, c2 = t & 15;
        __half2 v = (l < 49) ? qkv2[(size_t)(b * LTOK + l) * 768 + h * 16 + 512 + c2]
                             : __floats2half2_rn(0.f, 0.f);
        vt[(c2 * 2 + 0) * TPV + l] = __low2half(v);
        vt[(c2 * 2 + 1) * TPV + l] = __high2half(v);
    }
    __syncthreads();

    // ---- S = Q K^T (warp = 16-row slab), M=N=64, K=32
    const uint32_t sbq = smem_u32(qs), sbk = smem_u32(ks);
    const int ar = lane & 15;
    const int acolsel = (lane >> 4) << 4;
    const int br = (lane & 7) + ((lane >> 4) << 3);
    const int bcolsel = ((lane >> 3) & 1) << 4;

    float accs[8][4];
    #pragma unroll
    for (int ni = 0; ni < 8; ni++)
        #pragma unroll
        for (int e = 0; e < 4; e++) accs[ni][e] = 0.0f;

    #pragma unroll
    for (int kk = 0; kk < 2; kk++) {
        uint32_t af[4];
        ldmx4(af, sbq + (uint32_t)((wid * 16 + ar) * (TQK * 2) + kk * 32 + acolsel));
        uint32_t bf[4][4];
        #pragma unroll
        for (int nb = 0; nb < 4; nb++)
            ldmx4(bf[nb], sbk + (uint32_t)((nb * 16 + br) * (TQK * 2) + kk * 32 + bcolsel));
        #pragma unroll
        for (int ni = 0; ni < 8; ni++) {
            uint32_t b2[2] = {bf[ni >> 1][(ni & 1) * 2], bf[ni >> 1][(ni & 1) * 2 + 1]};
            mma16816(accs[ni], af, b2);
        }
    }

    // store S fragments to smem
    const int tr = lane >> 2, tc = (lane & 3) * 2;
    #pragma unroll
    for (int ni = 0; ni < 8; ni++) {
        int r = wid * 16 + tr, col = ni * 8 + tc;
        *(float2*)&sc[r * SCW + col] = make_float2(accs[ni][0], accs[ni][1]);
        *(float2*)&sc[(r + 8) * SCW + col] = make_float2(accs[ni][2], accs[ni][3]);
    }
    __syncthreads();

    // ---- softmax (fp32), P -> fp16 unnormalized, inv_sum per row
    const float* mrow = mask + (size_t)w * LL;
    const float* frow = g_fbias + (size_t)h * LL;
    for (int i = wid; i < LTOK; i += 4) {
        float m = -1e30f;
        for (int j = lane; j < LTOK; j += 32) {
            float v = sc[i * SCW + j] * scale + __ldg(&frow[i * LTOK + j]) + __ldg(&mrow[i * LTOK + j]);
            sc[i * SCW + j] = v;
            m = fmaxf(m, v);
        }
        #pragma unroll
        for (int o = 16; o; o >>= 1) m = fmaxf(m, __shfl_xor_sync(0xffffffffu, m, o));
        float sum = 0.0f;
        for (int j = lane; j < LTOK; j += 32) {
            float e = __expf(sc[i * SCW + j] - m);
            ph[i * TPV + j] = __float2half_rn(e);
            sum += e;
        }
        #pragma unroll
        for (int o = 16; o; o >>= 1) sum += __shfl_xor_sync(0xffffffffu, sum, o);
        if (lane == 0) inv_s[i] = 1.0f / sum;
    }
    __syncthreads();

    // ---- O = P V (M=64, N=32, K=64)
    const uint32_t sbp = smem_u32(ph), sbv = smem_u32(vt);
    float acco[4][4];
    #pragma unroll
    for (int ni = 0; ni < 4; ni++)
        #pragma unroll
        for (int e = 0; e < 4; e++) acco[ni][e] = 0.0f;

    #pragma unroll
    for (int kk = 0; kk < 4; kk++) {
        uint32_t af[4];
        ldmx4(af, sbp + (uint32_t)((wid * 16 + ar) * (TPV * 2) + kk * 32 + acolsel));
        uint32_t bf[2][4];
        #pragma unroll
        for (int nb = 0; nb < 2; nb++)
            ldmx4(bf[nb], sbv + (uint32_t)((nb * 16 + br) * (TPV * 2) + kk * 32 + bcolsel));
        #pragma unroll
        for (int ni = 0; ni < 4; ni++) {
            uint32_t b2[2] = {bf[ni >> 1][(ni & 1) * 2], bf[ni >> 1][(ni & 1) * 2 + 1]};
            mma16816(acco[ni], af, b2);
        }
    }

    // epilogue: normalize by inv_sum, store ctx fp16
    #pragma unroll
    for (int hr = 0; hr < 2; hr++) {
        int r = wid * 16 + tr + hr * 8;
        if (r < LTOK) {
            float is = inv_s[r];
            #pragma unroll
            for (int ni = 0; ni < 4; ni++) {
                int col = ni * 8 + tc;
                __half2 o = __floats2half2_rn(acco[ni][hr * 2] * is, acco[ni][hr * 2 + 1] * is);
                *(__half2*)&g_ctx_h[(size_t)(b * LTOK + r) * DMODEL + h * HDIM + col] = o;
            }
        }
    }
}

// ---------------------------------------------------------------------------
// Launch
// ---------------------------------------------------------------------------
extern "C" void kernel_launch(void* const* d_in, const int* in_sizes, int n_in,
                              void* d_out, int out_size)
{
    const float* x          = (const float*)d_in[0];
    const float* w_qkv      = (const float*)d_in[1];
    const float* b_qkv      = (const float*)d_in[2];
    const float* w_out      = (const float*)d_in[3];
    const float* b_out      = (const float*)d_in[4];
    const float* bias_table = (const float*)d_in[5];
    const float* mask       = (const float*)d_in[6];
    const int*   rel_index  = (const int*)d_in[7];
    float*       out        = (float*)d_out;

    __half *qkvh, *xh, *ch, *wqh, *woh;
    cudaGetSymbolAddress((void**)&qkvh, g_qkv_h);
    cudaGetSymbolAddress((void**)&xh, g_x_h);
    cudaGetSymbolAddress((void**)&ch, g_ctx_h);
    cudaGetSymbolAddress((void**)&wqh, g_wqkvT_h);
    cudaGetSymbolAddress((void**)&woh, g_woutT_h);

    static bool attr_set = false;
    if (!attr_set) {
        cudaFuncSetAttribute(gemm_mma<__half>, cudaFuncAttributeMaxDynamicSharedMemorySize, SM_TOTAL);
        cudaFuncSetAttribute(gemm_mma<float>, cudaFuncAttributeMaxDynamicSharedMemorySize, SM_TOTAL);
        attr_set = true;
    }

    // Prep
    int n4 = MROWS * DMODEL / 4;
    prep_half_x<<<(n4 + 255) / 256, 256>>>(x, xh, n4);
    prep_half_wT<<<(N_QKV * DMODEL + 255) / 256, 256>>>(w_qkv, wqh, DMODEL, N_QKV);
    prep_half_wT<<<(DMODEL * DMODEL + 255) / 256, 256>>>(w_out, woh, DMODEL, DMODEL);
    prep_bias<<<(NHEAD * LL + 255) / 256, 256>>>(bias_table, rel_index);

    // QKV projection (fp16 output)
    dim3 g1(N_QKV / GBN, MROWS / GBM);
    gemm_mma<__half><<<g1, 256, SM_TOTAL>>>(xh, wqh, b_qkv, qkvh, MROWS, N_QKV, DMODEL);

    // Tensor-core attention
    attn_tc<<<BS * NHEAD, 128>>>(mask);

    // Output projection (f32 output)
    dim3 g2(DMODEL / GBN, MROWS / GBM);
    gemm_mma<float><<<g2, 256, SM_TOTAL>>>(ch, woh, b_out, out, MROWS, DMODEL, DMODEL);
}

// round 7
// speedup vs baseline: 4.0768x; 1.0300x over previous
#include <cuda_runtime.h>
#include <cuda_fp16.h>
#include <math.h>
#include <stdint.h>

// Problem constants
#define BS     2048
#define LTOK   49
#define DMODEL 512
#define NHEAD  16
#define HDIM   32
#define NMASK  64
#define MROWS  (BS * LTOK)          // 100352
#define N_QKV  (3 * DMODEL)         // 1536
#define LL     (LTOK * LTOK)        // 2401

// Scratch (device globals: allocation-free per harness rules)
__device__ __half g_qkv_h[(size_t)MROWS * N_QKV];         // qkv as fp16
__device__ __half g_x_h[(size_t)MROWS * DMODEL];          // x as fp16
__device__ __half g_ctx_h[(size_t)MROWS * DMODEL];        // ctx as fp16
__device__ __half g_wqkvT_h[(size_t)N_QKV * DMODEL];      // W^T [N,K] fp16
__device__ __half g_woutT_h[(size_t)DMODEL * DMODEL];
__device__ float g_fbias[NHEAD * LL];                     // fused rel-pos bias [H][L*L]

// ---------------------------------------------------------------------------
// PTX helpers (sm_80-compatible: cp.async + ldmatrix + mma.sync only)
// ---------------------------------------------------------------------------
__device__ __forceinline__ uint32_t smem_u32(const void* p) {
    uint32_t a;
    asm("{ .reg .u64 t; cvta.to.shared.u64 t, %1; cvt.u32.u64 %0, t; }" : "=r"(a) : "l"(p));
    return a;
}
#define CP_ASYNC16(dst, src) \
    asm volatile("cp.async.cg.shared.global [%0], [%1], 16;" :: "r"(dst), "l"(src))
#define CP_COMMIT() asm volatile("cp.async.commit_group;" ::: "memory")
#define CP_WAIT(n)  asm volatile("cp.async.wait_group %0;" :: "n"(n) : "memory")

__device__ __forceinline__ void ldmx4(uint32_t* r, uint32_t addr) {
    asm volatile("ldmatrix.sync.aligned.m8n8.x4.shared.b16 {%0,%1,%2,%3}, [%4];"
                 : "=r"(r[0]), "=r"(r[1]), "=r"(r[2]), "=r"(r[3]) : "r"(addr));
}
__device__ __forceinline__ void mma16816(float* d, const uint32_t* a, const uint32_t* b) {
    asm volatile(
        "mma.sync.aligned.m16n8k16.row.col.f32.f16.f16.f32 "
        "{%0,%1,%2,%3}, {%4,%5,%6,%7}, {%8,%9}, {%0,%1,%2,%3};"
        : "+f"(d[0]), "+f"(d[1]), "+f"(d[2]), "+f"(d[3])
        : "r"(a[0]), "r"(a[1]), "r"(a[2]), "r"(a[3]), "r"(b[0]), "r"(b[1]));
}

// SW64 swizzle for 64-byte smem rows: conflict-free ldmatrix + cp.async
__device__ __forceinline__ uint32_t sw64(int row, int bytecol) {
    return (uint32_t)(row * 64 + (bytecol ^ ((row & 6) << 3)));
}

// ---------------------------------------------------------------------------
// Prep kernels
// ---------------------------------------------------------------------------
__global__ void prep_half_x(const float* __restrict__ x,
                            __half* __restrict__ out, int n4)
{
    int i = blockIdx.x * blockDim.x + threadIdx.x;
    if (i >= n4) return;
    float4 v = ((const float4*)x)[i];
    ((__half2*)out)[i * 2 + 0] = __floats2half2_rn(v.x, v.y);
    ((__half2*)out)[i * 2 + 1] = __floats2half2_rn(v.z, v.w);
}

__global__ void prep_half_wT(const float* __restrict__ W,
                             __half* __restrict__ Wt, int K, int N)
{
    int idx = blockIdx.x * blockDim.x + threadIdx.x;   // n*K + k
    if (idx >= K * N) return;
    int n = idx / K, k = idx - n * K;
    Wt[idx] = __float2half_rn(W[(size_t)k * N + n]);
}

__global__ void prep_bias(const float* __restrict__ bias_table,
                          const int* __restrict__ rel_index)
{
    int i = blockIdx.x * blockDim.x + threadIdx.x;
    if (i >= NHEAD * LL) return;
    int h = i / LL, idx = i - h * LL;
    g_fbias[i] = bias_table[rel_index[idx] * NHEAD + h];
}

// ---------------------------------------------------------------------------
// mma.sync GEMM: C[M,N] = A[M,K](fp16) @ B[N,K](fp16)^T + bias (fp32 acc)
// 128x128 CTA tile, 4 warps (warp tile 64x64), BK=32, 128 threads,
// 5-stage cp.async pipeline, 2 CTAs/SM. OutT = float or __half.
// ---------------------------------------------------------------------------
#define GBM 128
#define GBN 128
#define GBK 32
#define TILEB (128 * 64)                // 8192
#define STAGEB (2 * TILEB)              // 16384 (A + B)
#define NSTAGE 5
#define SM_A 0
#define SM_B TILEB
#define SM_TOTAL (NSTAGE * STAGEB)      // 81920

template <typename OutT>
__global__ __launch_bounds__(128, 2) void gemm_mma(
    const __half* __restrict__ A, const __half* __restrict__ B,
    const float* __restrict__ bias, OutT* __restrict__ C,
    int M, int N, int K)
{
    extern __shared__ char smem[];
    const uint32_t sbase = smem_u32(smem);
    const int tid = threadIdx.x;
    const int lane = tid & 31;
    const int wid = tid >> 5;
    const int warp_m = wid & 1;         // 2 row-warps (64 rows each)
    const int warp_n = wid >> 1;        // 2 col-warps (64 cols each)
    const int bm = blockIdx.y * GBM;
    const int bn = blockIdx.x * GBN;

    float acc[4][8][4];
    #pragma unroll
    for (int mi = 0; mi < 4; mi++)
        #pragma unroll
        for (int ni = 0; ni < 8; ni++)
            #pragma unroll
            for (int e = 0; e < 4; e++) acc[mi][ni][e] = 0.0f;

    const int nch = K / GBK;            // 16

    // stage loader: 2 tiles x 512 x 16B chunks / 128 threads = 8 cp.async/thread
    auto load_stage = [&](int ch, int s) {
        const int k0 = ch * GBK;
        const uint32_t stbase = sbase + (uint32_t)s * STAGEB;
        #pragma unroll
        for (int i = 0; i < 4; i++) {
            int u = tid + i * 128;
            int row = u >> 2, c = u & 3;
            const void* srcA = A + (size_t)(bm + row) * K + k0 + c * 8;
            CP_ASYNC16(stbase + SM_A + sw64(row, c * 16), srcA);
            const void* srcB = B + (size_t)(bn + row) * K + k0 + c * 8;
            CP_ASYNC16(stbase + SM_B + sw64(row, c * 16), srcB);
        }
        CP_COMMIT();
    };

    load_stage(0, 0);
    load_stage(1, 1);
    load_stage(2, 2);
    load_stage(3, 3);

    int slot = 0;
    for (int ch = 0; ch < nch; ch++) {
        if (ch + 3 < nch)      { CP_WAIT(3); }
        else if (ch + 2 < nch) { CP_WAIT(2); }
        else if (ch + 1 < nch) { CP_WAIT(1); }
        else                   { CP_WAIT(0); }
        __syncthreads();
        if (ch + 4 < nch) load_stage(ch + 4, (slot + 4) % NSTAGE);

        const uint32_t st = sbase + (uint32_t)slot * STAGEB;
        #pragma unroll
        for (int kk = 0; kk < 2; kk++) {
            uint32_t a_f[4][4], b_f[4][4];
            const int ar = lane & 15;
            const int abyte = kk * 32 + ((lane >> 4) << 4);
            #pragma unroll
            for (int mi = 0; mi < 4; mi++)
                ldmx4(a_f[mi], st + SM_A + sw64(warp_m * 64 + mi * 16 + ar, abyte));
            const int br = (lane & 7) + ((lane >> 4) << 3);
            const int bbyte = kk * 32 + (((lane >> 3) & 1) << 4);
            #pragma unroll
            for (int nb = 0; nb < 4; nb++)
                ldmx4(b_f[nb], st + SM_B + sw64(warp_n * 64 + nb * 16 + br, bbyte));
            #pragma unroll
            for (int mi = 0; mi < 4; mi++) {
                #pragma unroll
                for (int ni = 0; ni < 8; ni++) {
                    const int nb = ni >> 1, hf = (ni & 1) * 2;
                    uint32_t b2[2] = {b_f[nb][hf], b_f[nb][hf + 1]};
                    mma16816(acc[mi][ni], a_f[mi], b2);
                }
            }
        }
        slot = (slot + 1) % NSTAGE;
    }

    // Epilogue
    const int tr = lane >> 2;
    const int tc = (lane & 3) * 2;
    #pragma unroll
    for (int mi = 0; mi < 4; mi++) {
        const int r0 = bm + warp_m * 64 + mi * 16 + tr;
        #pragma unroll
        for (int ni = 0; ni < 8; ni++) {
            const int col = bn + warp_n * 64 + ni * 8 + tc;
            const float b0 = __ldg(&bias[col]);
            const float b1 = __ldg(&bias[col + 1]);
            float v00 = acc[mi][ni][0] + b0, v01 = acc[mi][ni][1] + b1;
            float v10 = acc[mi][ni][2] + b0, v11 = acc[mi][ni][3] + b1;
            if (sizeof(OutT) == 2) {
                *(__half2*)((__half*)C + (size_t)r0 * N + col) = __floats2half2_rn(v00, v01);
                *(__half2*)((__half*)C + (size_t)(r0 + 8) * N + col) = __floats2half2_rn(v10, v11);
            } else {
                *(float2*)((float*)C + (size_t)r0 * N + col) = make_float2(v00, v01);
                *(float2*)((float*)C + (size_t)(r0 + 8) * N + col) = make_float2(v10, v11);
            }
        }
    }
}

// ---------------------------------------------------------------------------
// Tensor-core attention: one block per (window b, head h), 128 threads (4 warps).
// S = Q K^T via mma (fp16 in, fp32 acc), softmax fp32, O = P V via mma.
// 49 padded to 64 rows/cols; padding kept inert via zeroed P cols / V rows.
// ---------------------------------------------------------------------------
#define TQK 40    // half stride for q/k rows (80 B, conflict-free ldmatrix)
#define SCW 66    // f32 stride for score rows (264 B)
#define TPV 72    // half stride for p/vt rows (144 B, conflict-free ldmatrix)

__global__ __launch_bounds__(128) void attn_tc(const float* __restrict__ mask)
{
    __shared__ __half qs[64 * TQK];
    __shared__ __half ks[64 * TQK];
    __shared__ __half vt[32 * TPV];     // V^T: [c][l]
    __shared__ float  sc[64 * SCW];
    __shared__ __half ph[64 * TPV];     // unnormalized exp(P), fp16
    __shared__ float  inv_s[64];

    const int bh = blockIdx.x;
    const int b = bh >> 4, h = bh & 15, w = bh & (NMASK - 1);
    const int tid = threadIdx.x, lane = tid & 31, wid = tid >> 5;
    const float scale = 0.17677669529663687f;   // 1/sqrt(32)

    // zero ph (padding rows/cols must stay zero)
    for (int i = tid; i < 64 * TPV / 2; i += 128)
        ((uint32_t*)ph)[i] = 0u;

    // load q, k (rows < 49; pad rows only feed unused S entries)
    const __half2* qkv2 = (const __half2*)g_qkv_h;
    for (int t = tid; t < 49 * 16; t += 128) {
        int l = t >> 4, c2 = t & 15;
        size_t base = (size_t)(b * LTOK + l) * 768 + h * 16 + c2;
        *(__half2*)&qs[l * TQK + c2 * 2] = qkv2[base];
        *(__half2*)&ks[l * TQK + c2 * 2] = qkv2[base + 256];
    }
    // v transposed with zero pad for l in [49,64)
    for (int t = tid; t < 64 * 16; t += 128) {
        int l = t >> 4, c2 = t & 15;
        __half2 v = (l < 49) ? qkv2[(size_t)(b * LTOK + l) * 768 + h * 16 + 512 + c2]
                             : __floats2half2_rn(0.f, 0.f);
        vt[(c2 * 2 + 0) * TPV + l] = __low2half(v);
        vt[(c2 * 2 + 1) * TPV + l] = __high2half(v);
    }
    __syncthreads();

    // ---- S = Q K^T (warp = 16-row slab), M=N=64, K=32
    const uint32_t sbq = smem_u32(qs), sbk = smem_u32(ks);
    const int ar = lane & 15;
    const int acolsel = (lane >> 4) << 4;
    const int br = (lane & 7) + ((lane >> 4) << 3);
    const int bcolsel = ((lane >> 3) & 1) << 4;

    float accs[8][4];
    #pragma unroll
    for (int ni = 0; ni < 8; ni++)
        #pragma unroll
        for (int e = 0; e < 4; e++) accs[ni][e] = 0.0f;

    #pragma unroll
    for (int kk = 0; kk < 2; kk++) {
        uint32_t af[4];
        ldmx4(af, sbq + (uint32_t)((wid * 16 + ar) * (TQK * 2) + kk * 32 + acolsel));
        uint32_t bf[4][4];
        #pragma unroll
        for (int nb = 0; nb < 4; nb++)
            ldmx4(bf[nb], sbk + (uint32_t)((nb * 16 + br) * (TQK * 2) + kk * 32 + bcolsel));
        #pragma unroll
        for (int ni = 0; ni < 8; ni++) {
            uint32_t b2[2] = {bf[ni >> 1][(ni & 1) * 2], bf[ni >> 1][(ni & 1) * 2 + 1]};
            mma16816(accs[ni], af, b2);
        }
    }

    // store S fragments to smem
    const int tr = lane >> 2, tc = (lane & 3) * 2;
    #pragma unroll
    for (int ni = 0; ni < 8; ni++) {
        int r = wid * 16 + tr, col = ni * 8 + tc;
        *(float2*)&sc[r * SCW + col] = make_float2(accs[ni][0], accs[ni][1]);
        *(float2*)&sc[(r + 8) * SCW + col] = make_float2(accs[ni][2], accs[ni][3]);
    }
    __syncthreads();

    // ---- softmax (fp32), P -> fp16 unnormalized, inv_sum per row
    const float* mrow = mask + (size_t)w * LL;
    const float* frow = g_fbias + (size_t)h * LL;
    for (int i = wid; i < LTOK; i += 4) {
        float m = -1e30f;
        for (int j = lane; j < LTOK; j += 32) {
            float v = sc[i * SCW + j] * scale + __ldg(&frow[i * LTOK + j]) + __ldg(&mrow[i * LTOK + j]);
            sc[i * SCW + j] = v;
            m = fmaxf(m, v);
        }
        #pragma unroll
        for (int o = 16; o; o >>= 1) m = fmaxf(m, __shfl_xor_sync(0xffffffffu, m, o));
        float sum = 0.0f;
        for (int j = lane; j < LTOK; j += 32) {
            float e = __expf(sc[i * SCW + j] - m);
            ph[i * TPV + j] = __float2half_rn(e);
            sum += e;
        }
        #pragma unroll
        for (int o = 16; o; o >>= 1) sum += __shfl_xor_sync(0xffffffffu, sum, o);
        if (lane == 0) inv_s[i] = 1.0f / sum;
    }
    __syncthreads();

    // ---- O = P V (M=64, N=32, K=64)
    const uint32_t sbp = smem_u32(ph), sbv = smem_u32(vt);
    float acco[4][4];
    #pragma unroll
    for (int ni = 0; ni < 4; ni++)
        #pragma unroll
        for (int e = 0; e < 4; e++) acco[ni][e] = 0.0f;

    #pragma unroll
    for (int kk = 0; kk < 4; kk++) {
        uint32_t af[4];
        ldmx4(af, sbp + (uint32_t)((wid * 16 + ar) * (TPV * 2) + kk * 32 + acolsel));
        uint32_t bf[2][4];
        #pragma unroll
        for (int nb = 0; nb < 2; nb++)
            ldmx4(bf[nb], sbv + (uint32_t)((nb * 16 + br) * (TPV * 2) + kk * 32 + bcolsel));
        #pragma unroll
        for (int ni = 0; ni < 4; ni++) {
            uint32_t b2[2] = {bf[ni >> 1][(ni & 1) * 2], bf[ni >> 1][(ni & 1) * 2 + 1]};
            mma16816(acco[ni], af, b2);
        }
    }

    // epilogue: normalize by inv_sum, store ctx fp16
    #pragma unroll
    for (int hr = 0; hr < 2; hr++) {
        int r = wid * 16 + tr + hr * 8;
        if (r < LTOK) {
            float is = inv_s[r];
            #pragma unroll
            for (int ni = 0; ni < 4; ni++) {
                int col = ni * 8 + tc;
                __half2 o = __floats2half2_rn(acco[ni][hr * 2] * is, acco[ni][hr * 2 + 1] * is);
                *(__half2*)&g_ctx_h[(size_t)(b * LTOK + r) * DMODEL + h * HDIM + col] = o;
            }
        }
    }
}

// ---------------------------------------------------------------------------
// Launch
// ---------------------------------------------------------------------------
extern "C" void kernel_launch(void* const* d_in, const int* in_sizes, int n_in,
                              void* d_out, int out_size)
{
    const float* x          = (const float*)d_in[0];
    const float* w_qkv      = (const float*)d_in[1];
    const float* b_qkv      = (const float*)d_in[2];
    const float* w_out      = (const float*)d_in[3];
    const float* b_out      = (const float*)d_in[4];
    const float* bias_table = (const float*)d_in[5];
    const float* mask       = (const float*)d_in[6];
    const int*   rel_index  = (const int*)d_in[7];
    float*       out        = (float*)d_out;

    __half *qkvh, *xh, *ch, *wqh, *woh;
    cudaGetSymbolAddress((void**)&qkvh, g_qkv_h);
    cudaGetSymbolAddress((void**)&xh, g_x_h);
    cudaGetSymbolAddress((void**)&ch, g_ctx_h);
    cudaGetSymbolAddress((void**)&wqh, g_wqkvT_h);
    cudaGetSymbolAddress((void**)&woh, g_woutT_h);

    static bool attr_set = false;
    if (!attr_set) {
        cudaFuncSetAttribute(gemm_mma<__half>, cudaFuncAttributeMaxDynamicSharedMemorySize, SM_TOTAL);
        cudaFuncSetAttribute(gemm_mma<float>, cudaFuncAttributeMaxDynamicSharedMemorySize, SM_TOTAL);
        attr_set = true;
    }

    // Prep
    int n4 = MROWS * DMODEL / 4;
    prep_half_x<<<(n4 + 255) / 256, 256>>>(x, xh, n4);
    prep_half_wT<<<(N_QKV * DMODEL + 255) / 256, 256>>>(w_qkv, wqh, DMODEL, N_QKV);
    prep_half_wT<<<(DMODEL * DMODEL + 255) / 256, 256>>>(w_out, woh, DMODEL, DMODEL);
    prep_bias<<<(NHEAD * LL + 255) / 256, 256>>>(bias_table, rel_index);

    // QKV projection (fp16 output)
    dim3 g1(N_QKV / GBN, MROWS / GBM);
    gemm_mma<__half><<<g1, 128, SM_TOTAL>>>(xh, wqh, b_qkv, qkvh, MROWS, N_QKV, DMODEL);

    // Tensor-core attention
    attn_tc<<<BS * NHEAD, 128>>>(mask);

    // Output projection (f32 output)
    dim3 g2(DMODEL / GBN, MROWS / GBM);
    gemm_mma<float><<<g2, 128, SM_TOTAL>>>(ch, woh, b_out, out, MROWS, DMODEL, DMODEL);
}